// round 6
// baseline (speedup 1.0000x reference)
#include <cuda_runtime.h>

// Fixed shapes
#define HH 256
#define WW 512
#define HW (HH * WW)                 // 131072 floats/plane
#define HW4 (HW / 4)                 // 32768 float4/plane
#define W4 (WW / 4)                  // 128 float4/row
#define NSTUFF 11
#define STUFF_ELEMS (NSTUFF * HW)    // floats
#define STUFF4 (NSTUFF * HW4)
#define NBOX 128
#define SLICES 4                     // row-slices per box

// Fills only the in-box rectangle of each instance plane with gathered seg values.
// Runs AFTER the memset, so out-of-box lanes/pixels are already zero.
__global__ __launch_bounds__(256) void box_fill_kernel(
    const int*    __restrict__ cls,     // [128]
    const float*  __restrict__ seg,     // [19*HW]
    const float*  __restrict__ boxes,   // [128*5]
    float*        __restrict__ out)
{
    const int n     = blockIdx.x >> 2;        // box index
    const int slice = blockIdx.x & (SLICES - 1);

    const int c = __ldg(cls + n);
    if (c == 0) return;

    const float* bb = boxes + n * 5;
    const int x0 = (int)floorf(__ldg(bb + 1) * 0.25f);
    const int y0 = (int)floorf(__ldg(bb + 2) * 0.25f);
    const int x1 = (int)(rintf(__ldg(bb + 3) * 0.25f) + 1.0f);  // half-even = jnp.round
    const int y1 = (int)(rintf(__ldg(bb + 4) * 0.25f) + 1.0f);

    // Clamp to plane
    const int cx0 = max(x0, 0), cx1 = min(x1, WW);
    const int cy0 = max(y0, 0), cy1 = min(y1, HH);
    if (cx0 >= cx1 || cy0 >= cy1) return;

    // This slice's row range
    const int rows  = cy1 - cy0;
    const int rlo   = cy0 + (rows * slice) / SLICES;
    const int rhi   = cy0 + (rows * (slice + 1)) / SLICES;
    if (rlo >= rhi) return;

    const int m = (c + 10 > 18) ? 18 : c + 10;

    // float4 column range covering [cx0, cx1)
    const int f0 = cx0 >> 2;
    const int f1 = (cx1 + 3) >> 2;                 // exclusive

    const float4* s4 = reinterpret_cast<const float4*>(seg) + m * HW4;
    float4*       o4 = reinterpret_cast<float4*>(out) + STUFF4 + n * HW4;

    // blockDim = (32, 8): x covers f4 columns, y covers rows
    const int tx = threadIdx.x & 31;
    const int ty = threadIdx.x >> 5;

    for (int y = rlo + ty; y < rhi; y += 8) {
        const int rowb = y * W4;
        for (int f = f0 + tx; f < f1; f += 32) {
            float4 v = s4[rowb + f];
            const int x = f << 2;
            // Mask lanes outside [cx0, cx1) (overwrites memset zeros with zeros — safe)
            if (x + 0 < cx0 || x + 0 >= cx1) v.x = 0.f;
            if (x + 1 < cx0 || x + 1 >= cx1) v.y = 0.f;
            if (x + 2 < cx0 || x + 2 >= cx1) v.z = 0.f;
            if (x + 3 < cx0 || x + 3 >= cx1) v.w = 0.f;
            o4[rowb + f] = v;
        }
    }
}

extern "C" void kernel_launch(void* const* d_in, const int* in_sizes, int n_in,
                              void* d_out, int out_size)
{
    const int*   cls   = (const int*)d_in[0];
    const float* seg   = (const float*)d_in[1];
    const float* boxes = (const float*)d_in[2];
    float* out = (float*)d_out;

    // 1) Zero the 64 MB instance region with the driver's tuned memset.
    cudaMemsetAsync(out + STUFF_ELEMS, 0,
                    (size_t)NBOX * HW * sizeof(float), 0);

    // 2) Stuff copy: 5.8 MB device-to-device (explicitly allowed, driver-tuned).
    cudaMemcpyAsync(out, seg, (size_t)STUFF_ELEMS * sizeof(float),
                    cudaMemcpyDeviceToDevice, 0);

    // 3) Fill only the in-box rectangles (runs after memset in stream order).
    box_fill_kernel<<<NBOX * SLICES, 256>>>(cls, seg, boxes, out);
}

// round 7
// speedup vs baseline: 1.4289x; 1.4289x over previous
#include <cuda_runtime.h>
#include <cstdint>

// Fixed shapes
#define HH 256
#define WW 512
#define HW (HH * WW)                 // floats per plane
#define HW4 (HW / 4)                 // 32768 float4/plane
#define W4 (WW / 4)                  // 128 float4/row
#define NSTUFF 11
#define STUFF4 (NSTUFF * HW4)
#define TPB 256
#define ITEMS 8                      // float4 per thread per chunk
#define F4_PER_CHUNK (TPB * ITEMS)   // 2048 float4 = 32 KB = 16 rows
#define CHUNK_BYTES (F4_PER_CHUNK * 16)
#define ROWS_PER_CHUNK 16
#define STUFF_CHUNKS (STUFF4 / F4_PER_CHUNK)     // 176
#define CHUNKS_PER_PLANE (HW4 / F4_PER_CHUNK)    // 16
#define NBOX 128

__device__ __forceinline__ uint32_t smem_u32(const void* p) {
    return (uint32_t)__cvta_generic_to_shared(p);
}

__global__ __launch_bounds__(TPB) void seg_term_kernel(
    const int*    __restrict__ cls,     // [128]
    const float*  __restrict__ seg,     // [19*HW]
    const float*  __restrict__ boxes,   // [128*5]
    float*        __restrict__ out)
{
    __shared__ __align__(128) float4 zbuf[F4_PER_CHUNK];   // 32 KB of zeros

    const int tid = threadIdx.x;
    const int ch  = blockIdx.x;
    const float4 z = make_float4(0.f, 0.f, 0.f, 0.f);

    if (ch < STUFF_CHUNKS) {
        // ---- stuff copy chunk (proven R3 path): 8 batched loads, 8 stores ----
        const float4* s4 = reinterpret_cast<const float4*>(seg) + ch * F4_PER_CHUNK;
        float4*       o4 = reinterpret_cast<float4*>(out)       + ch * F4_PER_CHUNK;
        float4 v[ITEMS];
        #pragma unroll
        for (int k = 0; k < ITEMS; k++) v[k] = s4[tid + k * TPB];
        #pragma unroll
        for (int k = 0; k < ITEMS; k++) o4[tid + k * TPB] = v[k];
        return;
    }

    // Zero the SMEM buffer up front — independent work that overlaps the
    // dependent cls/boxes load chain below.
    #pragma unroll
    for (int k = 0; k < ITEMS; k++) zbuf[tid + k * TPB] = z;

    const int ic  = ch - STUFF_CHUNKS;
    const int n   = ic >> 4;                     // plane index
    const int blk = ic & (CHUNKS_PER_PLANE - 1);
    const int r0  = blk * ROWS_PER_CHUNK;

    float4* o4 = reinterpret_cast<float4*>(out) + STUFF4 + n * HW4 + blk * F4_PER_CHUNK;

    const int c = __ldg(cls + n);
    int x0 = 0, y0 = 0, x1 = 0, y1 = 0, m = -1;
    if (c != 0) {
        const float* bb = boxes + n * 5;
        x0 = (int)floorf(__ldg(bb + 1) * 0.25f);
        y0 = (int)floorf(__ldg(bb + 2) * 0.25f);
        x1 = (int)(rintf(__ldg(bb + 3) * 0.25f) + 1.0f);  // half-even = jnp.round
        y1 = (int)(rintf(__ldg(bb + 4) * 0.25f) + 1.0f);
        if (x1 > x0 && y1 > y0 && x1 > 0 && x0 < WW && y1 > 0 && y0 < HH)
            m = (c + 10 > 18) ? 18 : c + 10;
    }

    const bool inter = (m >= 0) && (y1 > r0) && (y0 < r0 + ROWS_PER_CHUNK);

    if (!inter) {
        // ---- pure-zero chunk: ONE 32 KB TMA bulk store from SMEM ----
        __syncthreads();                                   // zbuf writes visible
        if (tid == 0) {
            asm volatile("fence.proxy.async.shared::cta;" ::: "memory");
            asm volatile(
                "cp.async.bulk.global.shared::cta.bulk_group [%0], [%1], %2;"
                :: "l"(o4), "r"(smem_u32(zbuf)), "n"(CHUNK_BYTES)
                : "memory");
            asm volatile("cp.async.bulk.commit_group;" ::: "memory");
            asm volatile("cp.async.bulk.wait_group 0;" ::: "memory");
        }
        return;
    }

    // ---- box-intersecting chunk: proven R3 gather/mask STG path ----
    const float4* s4 = reinterpret_cast<const float4*>(seg) + m * HW4 + blk * F4_PER_CHUNK;

    const int x = (tid & (W4 - 1)) << 2;          // first scalar col of this float4
    const bool col_full = (x >= x0) && ((x + 3) < x1);
    const bool col_edge = !col_full && ((x + 3) >= x0) && (x < x1);

    float4 v[ITEMS];
    #pragma unroll
    for (int k = 0; k < ITEMS; k++) {
        const int idx = tid + k * TPB;
        const int y   = r0 + (idx >> 7);
        v[k] = z;
        if (y >= y0 && y < y1) {
            if (col_full) {
                v[k] = s4[idx];
            } else if (col_edge) {
                const float* sr = reinterpret_cast<const float*>(s4 + idx);
                float vv[4];
                #pragma unroll
                for (int j = 0; j < 4; j++) {
                    const int xx = x + j;
                    vv[j] = (xx >= x0 && xx < x1) ? sr[j] : 0.f;
                }
                v[k] = make_float4(vv[0], vv[1], vv[2], vv[3]);
            }
        }
    }
    #pragma unroll
    for (int k = 0; k < ITEMS; k++) o4[tid + k * TPB] = v[k];
}

extern "C" void kernel_launch(void* const* d_in, const int* in_sizes, int n_in,
                              void* d_out, int out_size)
{
    const int*   cls   = (const int*)d_in[0];
    const float* seg   = (const float*)d_in[1];
    const float* boxes = (const float*)d_in[2];
    float* out = (float*)d_out;

    const int blocks = STUFF_CHUNKS + NBOX * CHUNKS_PER_PLANE;  // 2224
    seg_term_kernel<<<blocks, TPB>>>(cls, seg, boxes, out);
}